// round 13
// baseline (speedup 1.0000x reference)
#include <cuda_runtime.h>
#include <cuda_fp16.h>
#include <cstdint>
#include <math.h>

// ---------------- device scratch (allocation-free) ----------------
__device__ __align__(16) __half g_xh [256 * 1024];   // fp16(x)
__device__ __align__(16) __half g_Wh [512 * 1024];   // fp16(W)
__device__ __align__(16) __half g_ub [512 * 1024];   // fp16(expm1(u[k][n])), [k][n]
__device__ __align__(16) __half g_Ef [256 * 512];    // fp16(E)
__device__ float g_rs[32 * 256];                     // per-(ntile,row) rowsums of E
__device__ unsigned g_count = 0;
__device__ unsigned g_epoch = 0;

// ---------------- helpers ----------------
__device__ __forceinline__ uint32_t smem_u32(const void* p) {
    uint32_t a;
    asm("{ .reg .u64 t; cvta.to.shared.u64 t, %1; cvt.u32.u64 %0, t; }" : "=r"(a) : "l"(p));
    return a;
}
__device__ __forceinline__ void cp16(uint32_t dst, const void* src) {
    asm volatile("cp.async.cg.shared.global [%0], [%1], 16;" :: "r"(dst), "l"(src) : "memory");
}
#define CP_COMMIT() asm volatile("cp.async.commit_group;" ::: "memory")
#define CP_WAITN(n) asm volatile("cp.async.wait_group %0;" :: "n"(n) : "memory")

__device__ __forceinline__ void ldsm4(uint32_t* r, uint32_t addr) {
    asm volatile("ldmatrix.sync.aligned.m8n8.x4.shared.b16 {%0,%1,%2,%3}, [%4];"
        : "=r"(r[0]), "=r"(r[1]), "=r"(r[2]), "=r"(r[3]) : "r"(addr));
}
__device__ __forceinline__ void ldsm4t(uint32_t* r, uint32_t addr) {
    asm volatile("ldmatrix.sync.aligned.m8n8.x4.trans.shared.b16 {%0,%1,%2,%3}, [%4];"
        : "=r"(r[0]), "=r"(r[1]), "=r"(r[2]), "=r"(r[3]) : "r"(addr));
}
__device__ __forceinline__ void mma_f16(float* c, const uint32_t* a, uint32_t b0, uint32_t b1) {
    asm volatile("mma.sync.aligned.m16n8k16.row.col.f32.f16.f16.f32 "
        "{%0,%1,%2,%3}, {%4,%5,%6,%7}, {%8,%9}, {%0,%1,%2,%3};"
        : "+f"(c[0]), "+f"(c[1]), "+f"(c[2]), "+f"(c[3])
        : "r"(a[0]), "r"(a[1]), "r"(a[2]), "r"(a[3]), "r"(b0), "r"(b1));
}

__device__ __forceinline__ uint32_t pack_h2(float a, float b) {
    __half2 h = __floats2half2_rn(a, b);
    return *(uint32_t*)&h;
}
__device__ __forceinline__ float expm1_small(float u) {       // u in [0,1e-3]
    return u * fmaf(u, fmaf(u, 0.16666667f, 0.5f), 1.0f);
}
__device__ __forceinline__ uint32_t poly_pack2(float a, float b) {
    return pack_h2(expm1_small(a), expm1_small(b));
}

// ---------------- smem layout ----------------
constexpr int P     = 136;                   // pitch for A/E 128-wide tiles (halves)
constexpr int PU    = 40;                    // pitch for u 32-wide tiles (halves)
constexpr int T1A   = 32 * P * 2;            // 8704 B
constexpr int T1Bt  = 16 * P * 2;            // 4352 B
constexpr int STG1B = T1A + T1Bt;            // 13056 B, 4 stages = 52224
constexpr int ET2B  = 32 * P * 2;            // 8704 B
constexpr int UT2B  = 128 * PU * 2;          // 10240 B
constexpr int STG2B = ET2B + UT2B;           // 18944 B, 4 stages = 75776
constexpr int RED_OFF = 4 * STG2B;           // 75776
constexpr int DSMEM   = RED_OFF + 12288 + 256;   // sred + rst

// ---------------- grid sync (epoch-based, replay-safe) ----------------
__device__ __forceinline__ void grid_sync(int tid, int nblocks) {
    __syncthreads();
    if (tid == 0) {
        __threadfence();
        unsigned e;
        asm volatile("ld.acquire.gpu.global.b32 %0, [%1];" : "=r"(e) : "l"(&g_epoch) : "memory");
        unsigned arrived = atomicAdd(&g_count, 1u) + 1u;
        if (arrived == (unsigned)nblocks) {
            atomicExch(&g_count, 0u);
            __threadfence();
            atomicAdd(&g_epoch, 1u);
        } else {
            unsigned cur;
            do {
                __nanosleep(64);
                asm volatile("ld.acquire.gpu.global.b32 %0, [%1];" : "=r"(cur) : "l"(&g_epoch) : "memory");
            } while (cur == e);
        }
        __threadfence();
    }
    __syncthreads();
}

// ============================================================
// Fused, 3 phases, 256 CTAs x 256 thr (2 CTAs/SM for latency overlap):
//  P0: convert x,W -> f16; u -> f16(expm1)
//  P1: E = exp(x@W^T), tiles 32Mx16N (8mt x 32nt), 4-stage cp.async
//  P2: y = E @ ub + rowsum + 512, tiles 32Mx32N, ldsm.trans B
// ============================================================
__global__ __launch_bounds__(256) void fused_kernel(
    const float* __restrict__ x, const float* __restrict__ W,
    const float* __restrict__ u, float* __restrict__ Y)
{
    extern __shared__ __align__(16) char smem[];
    const uint32_t sb = smem_u32(smem);
    float* sredf = (float*)(smem + RED_OFF);
    float* rst = (float*)(smem + RED_OFF + 12288);

    const int tid = threadIdx.x, lane = tid & 31, wid = tid >> 5;
    const int blk = blockIdx.x;
    const int nt = blk & 31;                 // 0..31
    const int mt = blk >> 5;                 // 0..7
    const int m0 = mt * 32;

    // =================== PHASE 0: convert ===================
    {
        const int g = blk * 256 + tid;                    // 0..65535
        float4 xv  = ((const float4*)x)[g];
        float4 wv0 = ((const float4*)W)[g];
        float4 wv1 = ((const float4*)W)[g + 65536];
        float4 uv0 = ((const float4*)u)[g];
        float4 uv1 = ((const float4*)u)[g + 65536];
        *(uint2*)&g_xh[g * 4] = make_uint2(pack_h2(xv.x, xv.y), pack_h2(xv.z, xv.w));
        *(uint2*)&g_Wh[g * 4] = make_uint2(pack_h2(wv0.x, wv0.y), pack_h2(wv0.z, wv0.w));
        *(uint2*)&g_Wh[(g + 65536) * 4] = make_uint2(pack_h2(wv1.x, wv1.y), pack_h2(wv1.z, wv1.w));
        *(uint2*)&g_ub[g * 4] = make_uint2(poly_pack2(uv0.x, uv0.y), poly_pack2(uv0.z, uv0.w));
        *(uint2*)&g_ub[(g + 65536) * 4] = make_uint2(poly_pack2(uv1.x, uv1.y), poly_pack2(uv1.z, uv1.w));
    }
    grid_sync(tid, (int)gridDim.x);

    // =================== PHASE 1: E = exp(x @ W^T), 32Mx16N ===================
    const int n0 = nt * 16;
    const int rowT = tid >> 4, segT = tid & 15;

    // A: rows rowT and rowT+16; B: rows rowT (16 rows)
    const __half* aS0 = g_xh + (m0 + rowT) * 1024 + segT * 8;
    const __half* aS1 = g_xh + (m0 + rowT + 16) * 1024 + segT * 8;
    const __half* bS  = g_Wh + (n0 + rowT) * 1024 + segT * 8;
    const uint32_t aD0 = sb + (uint32_t)((rowT * P + segT * 8) * 2);
    const uint32_t aD1 = sb + (uint32_t)(((rowT + 16) * P + segT * 8) * 2);
    const uint32_t bD  = sb + (uint32_t)(T1A + (rowT * P + segT * 8) * 2);

    #define G1_ISSUE(c) do { \
        const uint32_t _so = ((c) & 3) * STG1B; \
        cp16(aD0 + _so, aS0 + (c) * 128); \
        cp16(aD1 + _so, aS1 + (c) * 128); \
        cp16(bD  + _so, bS  + (c) * 128); \
        CP_COMMIT(); \
    } while (0)

    // 8 warps: wm in {0,1} (16 M rows), wk in {0..3} (k-split)
    const int wm = wid & 1, wk = wid >> 1;
    const int lrow = lane & 15;
    const int lk = (lane >> 4) << 3;
    const uint32_t aOff = (uint32_t)(((wm * 16 + lrow) * P + lk) * 2);
    const uint32_t bOff = (uint32_t)(T1A + (lrow * P + lk) * 2);

    float acc0[4] = {}, acc1[4] = {};

    G1_ISSUE(0); G1_ISSUE(1); G1_ISSUE(2);

    for (int c = 0; c < 8; c++) {
        if (c <= 5) CP_WAITN(2);
        else if (c == 6) CP_WAITN(1);
        else CP_WAITN(0);
        __syncthreads();
        if (c + 3 < 8) G1_ISSUE(c + 3);
        const uint32_t st = sb + (c & 3) * STG1B;
        #pragma unroll
        for (int j = 0; j < 2; j++) {
            const int ks = wk * 2 + j;
            uint32_t a[4], b[4];
            ldsm4(a, st + aOff + ks * 32);
            ldsm4(b, st + bOff + ks * 32);
            mma_f16(acc0, a, b[0], b[2]);
            mma_f16(acc1, a, b[1], b[3]);
        }
    }
    #undef G1_ISSUE

    // k-split reduction: sred1[6][32][8] (wk 1..3, wm 0..1)
    float (*sred1)[32][8] = (float(*)[32][8])sredf;
    __syncthreads();
    if (wk != 0) {
        #pragma unroll
        for (int i = 0; i < 4; i++) {
            sred1[(wk - 1) * 2 + wm][lane][i]     = acc0[i];
            sred1[(wk - 1) * 2 + wm][lane][4 + i] = acc1[i];
        }
    }
    __syncthreads();

    if (wk == 0) {
        #pragma unroll
        for (int q = 0; q < 3; q++)
            #pragma unroll
            for (int i = 0; i < 4; i++) {
                acc0[i] += sred1[q * 2 + wm][lane][i];
                acc1[i] += sred1[q * 2 + wm][lane][4 + i];
            }
        // epilogue: __expf, fp16 E, fp32 rowsum (warp owns full 16-col rows)
        const int qr = lane >> 2;
        const int qc = (lane & 3) * 2;
        const int mrow0 = m0 + wm * 16 + qr;
        const int mrow1 = mrow0 + 8;
        float p0 = 0.f, p1 = 0.f;
        #pragma unroll
        for (int g = 0; g < 2; g++) {
            float* acc = g ? acc1 : acc0;
            float e0 = __expf(acc[0]), e1 = __expf(acc[1]);
            float e2 = __expf(acc[2]), e3 = __expf(acc[3]);
            p0 += e0 + e1; p1 += e2 + e3;
            const int n = n0 + g * 8 + qc;
            *(uint32_t*)&g_Ef[mrow0 * 512 + n] = pack_h2(e0, e1);
            *(uint32_t*)&g_Ef[mrow1 * 512 + n] = pack_h2(e2, e3);
        }
        p0 += __shfl_xor_sync(0xFFFFFFFFu, p0, 1);
        p0 += __shfl_xor_sync(0xFFFFFFFFu, p0, 2);
        p1 += __shfl_xor_sync(0xFFFFFFFFu, p1, 1);
        p1 += __shfl_xor_sync(0xFFFFFFFFu, p1, 2);
        if ((lane & 3) == 0) {
            g_rs[nt * 256 + mrow0] = p0;
            g_rs[nt * 256 + mrow1] = p1;
        }
    }

    // =================== GRID SYNC ===================
    grid_sync(tid, (int)gridDim.x);

    // =================== PHASE 2: y = E @ ub + rowsum + 512, 32Mx32N ===================
    const int n0b = nt * 32;

    if (tid < 32) {
        float s = 512.0f;
        #pragma unroll
        for (int j = 0; j < 32; j++) s += g_rs[j * 256 + m0 + tid];
        rst[tid] = s;
    }

    // loaders: E 2 cp16/thread, u 2 cp16/thread per chunk (K=128)
    const __half* eS0 = g_Ef + (m0 + rowT) * 512 + segT * 8;
    const __half* eS1 = g_Ef + (m0 + rowT + 16) * 512 + segT * 8;
    const uint32_t eD0 = sb + (uint32_t)((rowT * P + segT * 8) * 2);
    const uint32_t eD1 = sb + (uint32_t)(((rowT + 16) * P + segT * 8) * 2);
    const int krT = tid >> 2, sgT = tid & 3;
    const __half* uS0 = g_ub + krT * 1024 + n0b + sgT * 8;
    const __half* uS1 = g_ub + (krT + 64) * 1024 + n0b + sgT * 8;
    const uint32_t uD0 = sb + (uint32_t)(ET2B + (krT * PU + sgT * 8) * 2);
    const uint32_t uD1 = sb + (uint32_t)(ET2B + ((krT + 64) * PU + sgT * 8) * 2);

    #define G2_ISSUE(c) do { \
        const uint32_t _so = (c) * STG2B; \
        cp16(eD0 + _so, eS0 + (c) * 128); \
        cp16(eD1 + _so, eS1 + (c) * 128); \
        cp16(uD0 + _so, uS0 + (c) * 128 * 1024); \
        cp16(uD1 + _so, uS1 + (c) * 128 * 1024); \
        CP_COMMIT(); \
    } while (0)

    const uint32_t a2Off = (uint32_t)(((wm * 16 + lrow) * P + lk) * 2);
    const int li = lane & 7, kbit = (lane >> 3) & 1, nq = lane >> 4;
    const uint32_t tOff = (uint32_t)((((kbit * 8 + li) * PU) + nq * 8) * 2);

    float acc[4][4] = {};

    G2_ISSUE(0); G2_ISSUE(1); G2_ISSUE(2); G2_ISSUE(3);

    #pragma unroll
    for (int c = 0; c < 4; c++) {
        if (c == 0) CP_WAITN(3);
        else if (c == 1) CP_WAITN(2);
        else if (c == 2) CP_WAITN(1);
        else CP_WAITN(0);
        __syncthreads();
        const uint32_t st = sb + c * STG2B;
        const uint32_t stU = st + ET2B;
        #pragma unroll
        for (int j = 0; j < 2; j++) {
            const int ks = wk * 2 + j;
            uint32_t a[4], bq0[4], bq1[4];
            ldsm4(a, st + a2Off + ks * 32);
            ldsm4t(bq0, stU + tOff + ks * 16 * PU * 2);
            ldsm4t(bq1, stU + tOff + ks * 16 * PU * 2 + 16 * 2);
            mma_f16(acc[0], a, bq0[0], bq0[1]);
            mma_f16(acc[1], a, bq0[2], bq0[3]);
            mma_f16(acc[2], a, bq1[0], bq1[1]);
            mma_f16(acc[3], a, bq1[2], bq1[3]);
        }
    }
    #undef G2_ISSUE

    // k-split reduction: sred2[6][32][16]
    float (*sred2)[32][16] = (float(*)[32][16])sredf;
    __syncthreads();
    if (wk != 0) {
        #pragma unroll
        for (int g = 0; g < 4; g++)
            #pragma unroll
            for (int i = 0; i < 4; i++)
                sred2[(wk - 1) * 2 + wm][lane][g * 4 + i] = acc[g][i];
    }
    __syncthreads();

    if (wk == 0) {
        #pragma unroll
        for (int q = 0; q < 3; q++)
            #pragma unroll
            for (int g = 0; g < 4; g++)
                #pragma unroll
                for (int i = 0; i < 4; i++)
                    acc[g][i] += sred2[q * 2 + wm][lane][g * 4 + i];

        const int qr = lane >> 2;
        const int qc = (lane & 3) * 2;
        const int mrow0 = m0 + wm * 16 + qr;
        const int mrow1 = mrow0 + 8;
        const float r0v = rst[wm * 16 + qr];
        const float r1v = rst[wm * 16 + qr + 8];
        #pragma unroll
        for (int g = 0; g < 4; g++) {
            const int n = n0b + g * 8 + qc;
            *(float2*)(Y + mrow0 * 1024 + n) = make_float2(acc[g][0] + r0v, acc[g][1] + r0v);
            *(float2*)(Y + mrow1 * 1024 + n) = make_float2(acc[g][2] + r1v, acc[g][3] + r1v);
        }
    }
}

// ============================================================
extern "C" void kernel_launch(void* const* d_in, const int* in_sizes, int n_in,
                              void* d_out, int out_size)
{
    const float* x = (const float*)d_in[0];   // 256 x 1024
    const float* W = (const float*)d_in[1];   // 512 x 1024
    const float* u = (const float*)d_in[2];   // 512 x 1024
    float* y = (float*)d_out;                 // 256 x 1024

    cudaFuncSetAttribute(fused_kernel, cudaFuncAttributeMaxDynamicSharedMemorySize, DSMEM);
    fused_kernel<<<256, 256, DSMEM>>>(x, W, u, y);
}

// round 14
// speedup vs baseline: 1.0052x; 1.0052x over previous
#include <cuda_runtime.h>
#include <cuda_fp16.h>
#include <cstdint>
#include <math.h>

// ---------------- device scratch (allocation-free) ----------------
__device__ __align__(16) __half g_xh [256 * 1024];   // fp16(x)
__device__ __align__(16) __half g_Wh [512 * 1024];   // fp16(W)
__device__ __align__(16) __half g_ub [512 * 1024];   // fp16(expm1(u[k][n])), [k][n]
__device__ __align__(16) __half g_Ef [256 * 512];    // fp16(E)
__device__ float g_rs[16 * 256];                     // per-(ntile,row) rowsums of E
__device__ unsigned g_count = 0;                     // grid-sync arrivals
__device__ unsigned g_epoch = 0;                     // grid-sync epoch (monotonic)

// ---------------- helpers ----------------
__device__ __forceinline__ uint32_t smem_u32(const void* p) {
    uint32_t a;
    asm("{ .reg .u64 t; cvta.to.shared.u64 t, %1; cvt.u32.u64 %0, t; }" : "=r"(a) : "l"(p));
    return a;
}
__device__ __forceinline__ void cp16(uint32_t dst, const void* src) {
    asm volatile("cp.async.cg.shared.global [%0], [%1], 16;" :: "r"(dst), "l"(src) : "memory");
}
#define CP_COMMIT() asm volatile("cp.async.commit_group;" ::: "memory")
#define CP_WAITN(n) asm volatile("cp.async.wait_group %0;" :: "n"(n) : "memory")

__device__ __forceinline__ void ldsm4(uint32_t* r, uint32_t addr) {
    asm volatile("ldmatrix.sync.aligned.m8n8.x4.shared.b16 {%0,%1,%2,%3}, [%4];"
        : "=r"(r[0]), "=r"(r[1]), "=r"(r[2]), "=r"(r[3]) : "r"(addr));
}
__device__ __forceinline__ void ldsm4t(uint32_t* r, uint32_t addr) {
    asm volatile("ldmatrix.sync.aligned.m8n8.x4.trans.shared.b16 {%0,%1,%2,%3}, [%4];"
        : "=r"(r[0]), "=r"(r[1]), "=r"(r[2]), "=r"(r[3]) : "r"(addr));
}
__device__ __forceinline__ void mma_f16(float* c, const uint32_t* a, uint32_t b0, uint32_t b1) {
    asm volatile("mma.sync.aligned.m16n8k16.row.col.f32.f16.f16.f32 "
        "{%0,%1,%2,%3}, {%4,%5,%6,%7}, {%8,%9}, {%0,%1,%2,%3};"
        : "+f"(c[0]), "+f"(c[1]), "+f"(c[2]), "+f"(c[3])
        : "r"(a[0]), "r"(a[1]), "r"(a[2]), "r"(a[3]), "r"(b0), "r"(b1));
}

__device__ __forceinline__ uint32_t pack_h2(float a, float b) {
    __half2 h = __floats2half2_rn(a, b);
    return *(uint32_t*)&h;
}
// expm1 for u in [0,1e-3]: 3 FFMA, no MUFU
__device__ __forceinline__ float expm1_small(float u) {
    return u * fmaf(u, fmaf(u, 0.16666667f, 0.5f), 1.0f);
}
__device__ __forceinline__ uint32_t poly_pack2(float a, float b) {
    return pack_h2(expm1_small(a), expm1_small(b));
}

// ---------------- smem layout ----------------
constexpr int P      = 136;                  // 16-bit elem row pitch (272 B)
constexpr int T1B    = 32 * P * 2;           // 8704 B  (one 32x128 f16 tile)
constexpr int STG1B  = 2 * T1B;              // 17408 B (A|B), 8 stages = 139264
constexpr int ET2B   = 32 * P * 2;           // 8704 B
constexpr int UT2B   = 128 * P * 2;          // 34816 B
constexpr int STG2B  = ET2B + UT2B;          // 43520 B, 4 stages = 174080
constexpr int RED_OFF = 4 * STG2B;           // 174080 (P1's 8 stages fit inside)
constexpr int DSMEM   = RED_OFF + 24576 + 256;

// ---------------- grid sync (epoch-based, replay-safe) ----------------
__device__ __forceinline__ void grid_sync(int tid, int nblocks) {
    __syncthreads();
    if (tid == 0) {
        __threadfence();
        unsigned e;
        asm volatile("ld.acquire.gpu.global.b32 %0, [%1];" : "=r"(e) : "l"(&g_epoch) : "memory");
        unsigned arrived = atomicAdd(&g_count, 1u) + 1u;
        if (arrived == (unsigned)nblocks) {
            atomicExch(&g_count, 0u);
            __threadfence();
            atomicAdd(&g_epoch, 1u);
        } else {
            unsigned cur;
            do {
                __nanosleep(64);
                asm volatile("ld.acquire.gpu.global.b32 %0, [%1];" : "=r"(cur) : "l"(&g_epoch) : "memory");
            } while (cur == e);
        }
        __threadfence();
    }
    __syncthreads();
}

// ============================================================
// Fused, 3 phases (R12 base + P1 full 8-stage prefetch):
//  P0: convert x,W -> f16; u -> f16(expm1)
//  P1: E = exp(x@W^T), 32Mx32N tiles, ALL 8 K-stages prefetched
//  P2: y = E @ ub + rowsum(E) + 512, 32Mx64N, ALL 4 stages prefetched
// 128 CTAs x 512 thr (16 warps: 2wn x 2wm x 4wk), 1 CTA/SM.
// ============================================================
__global__ __launch_bounds__(512) void fused_kernel(
    const float* __restrict__ x, const float* __restrict__ W,
    const float* __restrict__ u, float* __restrict__ Y)
{
    extern __shared__ __align__(16) char smem[];
    const uint32_t sb = smem_u32(smem);
    float* sredf = (float*)(smem + RED_OFF);

    const int tid = threadIdx.x, lane = tid & 31, wid = tid >> 5;
    const int blk = blockIdx.x;
    const int nt = blk & 15;
    const int m0 = (blk >> 4) * 32, n0 = nt * 32;

    // =================== PHASE 0: convert ===================
    {
        const int g = blk * 512 + tid;                    // 0..65535
        float4 xv  = ((const float4*)x)[g];
        float4 wv0 = ((const float4*)W)[g];
        float4 wv1 = ((const float4*)W)[g + 65536];
        float4 uv0 = ((const float4*)u)[g];
        float4 uv1 = ((const float4*)u)[g + 65536];
        *(uint2*)&g_xh[g * 4] = make_uint2(pack_h2(xv.x, xv.y), pack_h2(xv.z, xv.w));
        *(uint2*)&g_Wh[g * 4] = make_uint2(pack_h2(wv0.x, wv0.y), pack_h2(wv0.z, wv0.w));
        *(uint2*)&g_Wh[(g + 65536) * 4] = make_uint2(pack_h2(wv1.x, wv1.y), pack_h2(wv1.z, wv1.w));
        *(uint2*)&g_ub[g * 4] = make_uint2(poly_pack2(uv0.x, uv0.y), poly_pack2(uv0.z, uv0.w));
        *(uint2*)&g_ub[(g + 65536) * 4] = make_uint2(poly_pack2(uv1.x, uv1.y), poly_pack2(uv1.z, uv1.w));
    }
    grid_sync(tid, (int)gridDim.x);

    // =================== PHASE 1: E = exp(x @ W^T) ===================
    // loader: 2 cp16/thread/chunk (A: 32x128 f16 tile, B: same)
    const int rowT = tid >> 4;                 // 0..31
    const int segT = tid & 15;                 // 16B segment
    const __half* aS = g_xh + (m0 + rowT) * 1024 + segT * 8;
    const __half* bS = g_Wh + (n0 + rowT) * 1024 + segT * 8;
    const uint32_t aD = sb + (uint32_t)((rowT * P + segT * 8) * 2);
    const uint32_t bD = sb + (uint32_t)(T1B + (rowT * P + segT * 8) * 2);

    #define G1_ISSUE(c) do { \
        const uint32_t _so = (c) * STG1B; \
        cp16(aD + _so, aS + (c) * 128); \
        cp16(bD + _so, bS + (c) * 128); \
        CP_COMMIT(); \
    } while (0)

    // compute mapping: 16 warps = 2(wn) x 2(wm) x 4(wk)
    const int wn = wid & 1, wm = (wid >> 1) & 1, wk = wid >> 2;
    const int lrow = lane & 15;
    const int lk = (lane >> 4) << 3;
    const uint32_t aOff = (uint32_t)(((wm * 16 + lrow) * P + lk) * 2);
    const uint32_t bOff = (uint32_t)(T1B + ((wn * 16 + lrow) * P + lk) * 2);

    float acc0[4] = {}, acc1[4] = {};

    // prefetch ALL 8 stages (full K=1024)
    G1_ISSUE(0); G1_ISSUE(1); G1_ISSUE(2); G1_ISSUE(3);
    G1_ISSUE(4); G1_ISSUE(5); G1_ISSUE(6); G1_ISSUE(7);
    #undef G1_ISSUE

    #pragma unroll
    for (int c = 0; c < 8; c++) {
        switch (c) {
            case 0: CP_WAITN(7); break;
            case 1: CP_WAITN(6); break;
            case 2: CP_WAITN(5); break;
            case 3: CP_WAITN(4); break;
            case 4: CP_WAITN(3); break;
            case 5: CP_WAITN(2); break;
            case 6: CP_WAITN(1); break;
            default: CP_WAITN(0); break;
        }
        __syncthreads();
        const uint32_t st = sb + c * STG1B;
        #pragma unroll
        for (int j = 0; j < 2; j++) {
            const int ks = wk * 2 + j;         // 0..7 ksteps of 16
            uint32_t a[4], b[4];
            ldsm4(a, st + aOff + ks * 32);
            ldsm4(b, st + bOff + ks * 32);
            mma_f16(acc0, a, b[0], b[2]);
            mma_f16(acc1, a, b[1], b[3]);
        }
    }

    // 4-way k-split reduction: sred1[12][32][8]
    float (*sred1)[32][8] = (float(*)[32][8])sredf;
    float (*srs)[32] = (float(*)[32])(smem + RED_OFF + 12288);
    __syncthreads();
    if (wk != 0) {
        #pragma unroll
        for (int i = 0; i < 4; i++) {
            sred1[(wk - 1) * 4 + (wid & 3)][lane][i]     = acc0[i];
            sred1[(wk - 1) * 4 + (wid & 3)][lane][4 + i] = acc1[i];
        }
    }
    __syncthreads();

    if (wk == 0) {
        #pragma unroll
        for (int q = 0; q < 3; q++)
            #pragma unroll
            for (int i = 0; i < 4; i++) {
                acc0[i] += sred1[q * 4 + wid][lane][i];
                acc1[i] += sred1[q * 4 + wid][lane][4 + i];
            }
        // epilogue: __expf, fp16 E, fp32 rowsum
        const int qr = lane >> 2;
        const int qc = (lane & 3) * 2;
        const int mrow0 = m0 + wm * 16 + qr;
        const int mrow1 = mrow0 + 8;
        float p0 = 0.f, p1 = 0.f;
        #pragma unroll
        for (int g = 0; g < 2; g++) {
            float* acc = g ? acc1 : acc0;
            float e0 = __expf(acc[0]), e1 = __expf(acc[1]);
            float e2 = __expf(acc[2]), e3 = __expf(acc[3]);
            p0 += e0 + e1; p1 += e2 + e3;
            const int n = n0 + wn * 16 + g * 8 + qc;
            *(uint32_t*)&g_Ef[mrow0 * 512 + n] = pack_h2(e0, e1);
            *(uint32_t*)&g_Ef[mrow1 * 512 + n] = pack_h2(e2, e3);
        }
        p0 += __shfl_xor_sync(0xFFFFFFFFu, p0, 1);
        p0 += __shfl_xor_sync(0xFFFFFFFFu, p0, 2);
        p1 += __shfl_xor_sync(0xFFFFFFFFu, p1, 1);
        p1 += __shfl_xor_sync(0xFFFFFFFFu, p1, 2);
        if ((lane & 3) == 0) {
            srs[wn][wm * 16 + qr]     = p0;
            srs[wn][wm * 16 + qr + 8] = p1;
        }
    }
    __syncthreads();
    if (tid < 32) g_rs[nt * 256 + m0 + tid] = srs[0][tid] + srs[1][tid];

    // =================== GRID SYNC ===================
    grid_sync(tid, (int)gridDim.x);

    // =================== PHASE 2: y = E @ ub + rowsum + 512 ===================
    const int n0b = nt * 64;

    float* rst = (float*)(smem + RED_OFF + 24576);
    if (tid < 32) {
        float s = 512.0f;
        #pragma unroll
        for (int j = 0; j < 16; j++) s += g_rs[j * 256 + m0 + tid];
        rst[tid] = s;
    }

    // loaders: E 1 cp16/thread, u 2 cp16/thread per chunk (K=128 chunks)
    const int rowE = tid >> 4, segE = tid & 15;
    const __half* aSrc = g_Ef + (m0 + rowE) * 512 + segE * 8;
    const uint32_t aDst = sb + (uint32_t)((rowE * P + segE * 8) * 2);
    const int uIdx0 = tid * 2, uIdx1 = tid * 2 + 1;
    const int kr0 = uIdx0 >> 3, sg0 = uIdx0 & 7;
    const int kr1 = uIdx1 >> 3, sg1 = uIdx1 & 7;
    const __half* bSrc0 = g_ub + kr0 * 1024 + n0b + sg0 * 8;
    const __half* bSrc1 = g_ub + kr1 * 1024 + n0b + sg1 * 8;
    const uint32_t bDst0 = sb + (uint32_t)(ET2B + (kr0 * P + sg0 * 8) * 2);
    const uint32_t bDst1 = sb + (uint32_t)(ET2B + (kr1 * P + sg1 * 8) * 2);

    #define G2_ISSUE(c) do { \
        const uint32_t _so = (c) * STG2B; \
        cp16(aDst + _so, aSrc + (c) * 128); \
        cp16(bDst0 + _so, bSrc0 + (c) * 128 * 1024); \
        cp16(bDst1 + _so, bSrc1 + (c) * 128 * 1024); \
        CP_COMMIT(); \
    } while (0)

    const uint32_t a2Off = (uint32_t)(((wm * 16 + lrow) * P + lk) * 2);
    const int li = lane & 7, kbit = (lane >> 3) & 1, nq = lane >> 4;
    const uint32_t tOff = (uint32_t)((((kbit * 8 + li) * P) + nq * 8) * 2);

    float acc[4][4] = {};

    G2_ISSUE(0); G2_ISSUE(1); G2_ISSUE(2); G2_ISSUE(3);
    #undef G2_ISSUE

    #pragma unroll
    for (int c = 0; c < 4; c++) {
        if (c == 0) CP_WAITN(3);
        else if (c == 1) CP_WAITN(2);
        else if (c == 2) CP_WAITN(1);
        else CP_WAITN(0);
        __syncthreads();
        const uint32_t st = sb + c * STG2B;
        const uint32_t stU = st + ET2B;
        #pragma unroll
        for (int j = 0; j < 2; j++) {
            const int ks = wk * 2 + j;
            uint32_t a[4], bq0[4], bq1[4];
            ldsm4(a, st + a2Off + ks * 32);
            ldsm4t(bq0, stU + tOff + ks * 16 * P * 2 + (wn * 32 + 0) * 2);
            ldsm4t(bq1, stU + tOff + ks * 16 * P * 2 + (wn * 32 + 16) * 2);
            mma_f16(acc[0], a, bq0[0], bq0[1]);
            mma_f16(acc[1], a, bq0[2], bq0[3]);
            mma_f16(acc[2], a, bq1[0], bq1[1]);
            mma_f16(acc[3], a, bq1[2], bq1[3]);
        }
    }

    // k-split reduction: sred2[12][32][16]
    float (*sred2)[32][16] = (float(*)[32][16])sredf;
    __syncthreads();
    if (wk != 0) {
        #pragma unroll
        for (int g = 0; g < 4; g++)
            #pragma unroll
            for (int i = 0; i < 4; i++)
                sred2[(wk - 1) * 4 + (wid & 3)][lane][g * 4 + i] = acc[g][i];
    }
    __syncthreads();

    if (wk == 0) {
        #pragma unroll
        for (int q = 0; q < 3; q++)
            #pragma unroll
            for (int g = 0; g < 4; g++)
                #pragma unroll
                for (int i = 0; i < 4; i++)
                    acc[g][i] += sred2[q * 4 + wid][lane][g * 4 + i];

        const int qr = lane >> 2;
        const int qc = (lane & 3) * 2;
        const int mrow0 = m0 + wm * 16 + qr;
        const int mrow1 = mrow0 + 8;
        const float r0v = rst[wm * 16 + qr];
        const float r1v = rst[wm * 16 + qr + 8];
        #pragma unroll
        for (int g = 0; g < 4; g++) {
            const int n = n0b + wn * 32 + g * 8 + qc;
            *(float2*)(Y + mrow0 * 1024 + n) = make_float2(acc[g][0] + r0v, acc[g][1] + r0v);
            *(float2*)(Y + mrow1 * 1024 + n) = make_float2(acc[g][2] + r1v, acc[g][3] + r1v);
        }
    }
}

// ============================================================
extern "C" void kernel_launch(void* const* d_in, const int* in_sizes, int n_in,
                              void* d_out, int out_size)
{
    const float* x = (const float*)d_in[0];   // 256 x 1024
    const float* W = (const float*)d_in[1];   // 512 x 1024
    const float* u = (const float*)d_in[2];   // 512 x 1024
    float* y = (float*)d_out;                 // 256 x 1024

    cudaFuncSetAttribute(fused_kernel, cudaFuncAttributeMaxDynamicSharedMemorySize, DSMEM);
    fused_kernel<<<128, 512, DSMEM>>>(x, W, u, y);
}

// round 15
// speedup vs baseline: 1.1069x; 1.1011x over previous
#include <cuda_runtime.h>
#include <cuda_fp16.h>
#include <cstdint>
#include <math.h>

// ---------------- device scratch (allocation-free) ----------------
__device__ __align__(16) __half g_xh [256 * 1024];   // fp16(x)
__device__ __align__(16) __half g_Wh [512 * 1024];   // fp16(W)
__device__ __align__(16) __half g_ub [512 * 1024];   // fp16(expm1(u[k][n])), [k][n]
__device__ __align__(16) __half g_Ef [256 * 512];    // fp16(E)
__device__ float g_rs[16 * 256];                     // per-(ntile,row) rowsums of E
// monotonic producer counters (replay-safe via ticket targets; never reset)
__device__ unsigned g_xcnt[8];
__device__ unsigned g_wcnt[16];
__device__ unsigned g_ecnt[8];
__device__ unsigned g_ucnt;

// ---------------- helpers ----------------
__device__ __forceinline__ uint32_t smem_u32(const void* p) {
    uint32_t a;
    asm("{ .reg .u64 t; cvta.to.shared.u64 t, %1; cvt.u32.u64 %0, t; }" : "=r"(a) : "l"(p));
    return a;
}
__device__ __forceinline__ void cp16(uint32_t dst, const void* src) {
    asm volatile("cp.async.cg.shared.global [%0], [%1], 16;" :: "r"(dst), "l"(src) : "memory");
}
#define CP_COMMIT() asm volatile("cp.async.commit_group;" ::: "memory")
#define CP_WAITN(n) asm volatile("cp.async.wait_group %0;" :: "n"(n) : "memory")

__device__ __forceinline__ void ldsm4(uint32_t* r, uint32_t addr) {
    asm volatile("ldmatrix.sync.aligned.m8n8.x4.shared.b16 {%0,%1,%2,%3}, [%4];"
        : "=r"(r[0]), "=r"(r[1]), "=r"(r[2]), "=r"(r[3]) : "r"(addr));
}
__device__ __forceinline__ void ldsm4t(uint32_t* r, uint32_t addr) {
    asm volatile("ldmatrix.sync.aligned.m8n8.x4.trans.shared.b16 {%0,%1,%2,%3}, [%4];"
        : "=r"(r[0]), "=r"(r[1]), "=r"(r[2]), "=r"(r[3]) : "r"(addr));
}
__device__ __forceinline__ void mma_f16(float* c, const uint32_t* a, uint32_t b0, uint32_t b1) {
    asm volatile("mma.sync.aligned.m16n8k16.row.col.f32.f16.f16.f32 "
        "{%0,%1,%2,%3}, {%4,%5,%6,%7}, {%8,%9}, {%0,%1,%2,%3};"
        : "+f"(c[0]), "+f"(c[1]), "+f"(c[2]), "+f"(c[3])
        : "r"(a[0]), "r"(a[1]), "r"(a[2]), "r"(a[3]), "r"(b0), "r"(b1));
}

__device__ __forceinline__ uint32_t pack_h2(float a, float b) {
    __half2 h = __floats2half2_rn(a, b);
    return *(uint32_t*)&h;
}
// expm1 for u in [0,1e-3]: 3 FFMA, no MUFU
__device__ __forceinline__ float expm1_small(float u) {
    return u * fmaf(u, fmaf(u, 0.16666667f, 0.5f), 1.0f);
}
__device__ __forceinline__ uint32_t poly_pack2(float a, float b) {
    return pack_h2(expm1_small(a), expm1_small(b));
}

// release-ordered arrival; returns ticket (old value)
__device__ __forceinline__ unsigned atom_add_release(unsigned* p) {
    unsigned old;
    asm volatile("atom.add.release.gpu.u32 %0, [%1], %2;"
        : "=r"(old) : "l"(p), "r"(1u) : "memory");
    return old;
}
// spin until *cnt >= target (wrap-safe compare)
__device__ __forceinline__ void spin_until(const unsigned* cnt, unsigned target) {
    unsigned v;
    while (true) {
        asm volatile("ld.acquire.gpu.global.b32 %0, [%1];" : "=r"(v) : "l"(cnt) : "memory");
        if ((int)(v - target) >= 0) break;
        __nanosleep(32);
    }
}

// ---------------- smem layout ----------------
constexpr int P      = 136;                  // 16-bit elem row pitch (272 B)
constexpr int T1B    = 32 * P * 2;           // 8704 B  (one 32x128 f16 tile)
constexpr int STG1B  = 2 * T1B;              // 17408 B (A|B), 8 stages = 139264
constexpr int ET2B   = 32 * P * 2;           // 8704 B
constexpr int UT2B   = 128 * P * 2;          // 34816 B
constexpr int STG2B  = ET2B + UT2B;          // 43520 B, 4 stages = 174080
constexpr int RED_OFF = 4 * STG2B;           // 174080 (P1's 8 stages fit inside)
constexpr int DSMEM   = RED_OFF + 24576 + 256;

// ============================================================
// Fused, flag-synchronized (NO full grid syncs):
//  P0: tile-owned conversion  x,W -> f16; u -> f16(expm1)
//  P1: E = exp(x@W^T), 32Mx32N tiles, 8-stage prefetch   [waits x_cnt, w_cnt]
//  P2: y = E @ ub + rowsum(E) + 512, 32Mx64N             [waits e_cnt, u_cnt]
// 128 CTAs x 512 thr (16 warps: 2wn x 2wm x 4wk), 1 CTA/SM.
// ============================================================
__global__ __launch_bounds__(512) void fused_kernel(
    const float* __restrict__ x, const float* __restrict__ W,
    const float* __restrict__ u, float* __restrict__ Y)
{
    extern __shared__ __align__(16) char smem[];
    const uint32_t sb = smem_u32(smem);
    float* sredf = (float*)(smem + RED_OFF);

    const int tid = threadIdx.x, lane = tid & 31, wid = tid >> 5;
    const int blk = blockIdx.x;
    const int nt = blk & 15;
    const int mt = blk >> 4;
    const int m0 = mt * 32, n0 = nt * 32;

    // thread-0 sync state (tickets/targets)
    unsigned tu_target = 0;

    // =================== PHASE 0: tile-owned conversion ===================
    {
        // x: this CTA converts segment nt of x-tile mt (1 f4/thread)
        const int ix = mt * 8192 + nt * 512 + tid;
        float4 xv = ((const float4*)x)[ix];
        // W: segment mt of W-tile nt (2 consecutive f4/thread)
        const int iw = nt * 8192 + mt * 1024 + tid * 2;
        float4 wv0 = ((const float4*)W)[iw];
        float4 wv1 = ((const float4*)W)[iw + 1];
        // u: linear 1/128 (2 consecutive f4/thread)
        const int iu = blk * 1024 + tid * 2;
        float4 uv0 = ((const float4*)u)[iu];
        float4 uv1 = ((const float4*)u)[iu + 1];

        *(uint2*)&g_xh[ix * 4] = make_uint2(pack_h2(xv.x, xv.y), pack_h2(xv.z, xv.w));
        *(uint4*)&g_Wh[iw * 4] = make_uint4(pack_h2(wv0.x, wv0.y), pack_h2(wv0.z, wv0.w),
                                            pack_h2(wv1.x, wv1.y), pack_h2(wv1.z, wv1.w));
        *(uint4*)&g_ub[iu * 4] = make_uint4(poly_pack2(uv0.x, uv0.y), poly_pack2(uv0.z, uv0.w),
                                            poly_pack2(uv1.x, uv1.y), poly_pack2(uv1.z, uv1.w));
    }
    __threadfence();
    __syncthreads();
    if (tid == 0) {
        unsigned vx = atom_add_release(&g_xcnt[mt]);
        unsigned vw = atom_add_release(&g_wcnt[nt]);
        unsigned vu = atom_add_release(&g_ucnt);
        tu_target = vu - (vu & 127u) + 128u;
        spin_until(&g_xcnt[mt], vx - (vx & 15u) + 16u);
        spin_until(&g_wcnt[nt], vw - (vw & 7u) + 8u);
    }
    __syncthreads();

    // =================== PHASE 1: E = exp(x @ W^T) ===================
    const int rowT = tid >> 4;                 // 0..31
    const int segT = tid & 15;                 // 16B segment
    const __half* aS = g_xh + (m0 + rowT) * 1024 + segT * 8;
    const __half* bS = g_Wh + (n0 + rowT) * 1024 + segT * 8;
    const uint32_t aD = sb + (uint32_t)((rowT * P + segT * 8) * 2);
    const uint32_t bD = sb + (uint32_t)(T1B + (rowT * P + segT * 8) * 2);

    #define G1_ISSUE(c) do { \
        const uint32_t _so = (c) * STG1B; \
        cp16(aD + _so, aS + (c) * 128); \
        cp16(bD + _so, bS + (c) * 128); \
        CP_COMMIT(); \
    } while (0)

    // compute mapping: 16 warps = 2(wn) x 2(wm) x 4(wk)
    const int wn = wid & 1, wm = (wid >> 1) & 1, wk = wid >> 2;
    const int lrow = lane & 15;
    const int lk = (lane >> 4) << 3;
    const uint32_t aOff = (uint32_t)(((wm * 16 + lrow) * P + lk) * 2);
    const uint32_t bOff = (uint32_t)(T1B + ((wn * 16 + lrow) * P + lk) * 2);

    float acc0[4] = {}, acc1[4] = {};

    // prefetch ALL 8 stages (full K=1024)
    G1_ISSUE(0); G1_ISSUE(1); G1_ISSUE(2); G1_ISSUE(3);
    G1_ISSUE(4); G1_ISSUE(5); G1_ISSUE(6); G1_ISSUE(7);
    #undef G1_ISSUE

    #pragma unroll
    for (int c = 0; c < 8; c++) {
        switch (c) {
            case 0: CP_WAITN(7); break;
            case 1: CP_WAITN(6); break;
            case 2: CP_WAITN(5); break;
            case 3: CP_WAITN(4); break;
            case 4: CP_WAITN(3); break;
            case 5: CP_WAITN(2); break;
            case 6: CP_WAITN(1); break;
            default: CP_WAITN(0); break;
        }
        __syncthreads();
        const uint32_t st = sb + c * STG1B;
        #pragma unroll
        for (int j = 0; j < 2; j++) {
            const int ks = wk * 2 + j;         // 0..7 ksteps of 16
            uint32_t a[4], b[4];
            ldsm4(a, st + aOff + ks * 32);
            ldsm4(b, st + bOff + ks * 32);
            mma_f16(acc0, a, b[0], b[2]);
            mma_f16(acc1, a, b[1], b[3]);
        }
    }

    // 4-way k-split reduction: sred1[12][32][8]
    float (*sred1)[32][8] = (float(*)[32][8])sredf;
    float (*srs)[32] = (float(*)[32])(smem + RED_OFF + 12288);
    __syncthreads();
    if (wk != 0) {
        #pragma unroll
        for (int i = 0; i < 4; i++) {
            sred1[(wk - 1) * 4 + (wid & 3)][lane][i]     = acc0[i];
            sred1[(wk - 1) * 4 + (wid & 3)][lane][4 + i] = acc1[i];
        }
    }
    __syncthreads();

    if (wk == 0) {
        #pragma unroll
        for (int q = 0; q < 3; q++)
            #pragma unroll
            for (int i = 0; i < 4; i++) {
                acc0[i] += sred1[q * 4 + wid][lane][i];
                acc1[i] += sred1[q * 4 + wid][lane][4 + i];
            }
        // epilogue: __expf, fp16 E, fp32 rowsum
        const int qr = lane >> 2;
        const int qc = (lane & 3) * 2;
        const int mrow0 = m0 + wm * 16 + qr;
        const int mrow1 = mrow0 + 8;
        float p0 = 0.f, p1 = 0.f;
        #pragma unroll
        for (int g = 0; g < 2; g++) {
            float* acc = g ? acc1 : acc0;
            float e0 = __expf(acc[0]), e1 = __expf(acc[1]);
            float e2 = __expf(acc[2]), e3 = __expf(acc[3]);
            p0 += e0 + e1; p1 += e2 + e3;
            const int n = n0 + wn * 16 + g * 8 + qc;
            *(uint32_t*)&g_Ef[mrow0 * 512 + n] = pack_h2(e0, e1);
            *(uint32_t*)&g_Ef[mrow1 * 512 + n] = pack_h2(e2, e3);
        }
        p0 += __shfl_xor_sync(0xFFFFFFFFu, p0, 1);
        p0 += __shfl_xor_sync(0xFFFFFFFFu, p0, 2);
        p1 += __shfl_xor_sync(0xFFFFFFFFu, p1, 1);
        p1 += __shfl_xor_sync(0xFFFFFFFFu, p1, 2);
        if ((lane & 3) == 0) {
            srs[wn][wm * 16 + qr]     = p0;
            srs[wn][wm * 16 + qr + 8] = p1;
        }
    }
    __syncthreads();
    if (tid < 32) g_rs[nt * 256 + m0 + tid] = srs[0][tid] + srs[1][tid];

    // =================== E ready: arrive + wait for same-mt peers ===================
    __threadfence();
    __syncthreads();
    if (tid == 0) {
        unsigned ve = atom_add_release(&g_ecnt[mt]);
        spin_until(&g_ecnt[mt], ve - (ve & 15u) + 16u);
        spin_until(&g_ucnt, tu_target);       // long satisfied by now
    }
    __syncthreads();

    // =================== PHASE 2: y = E @ ub + rowsum + 512 ===================
    const int n0b = nt * 64;

    float* rst = (float*)(smem + RED_OFF + 24576);
    if (tid < 32) {
        float s = 512.0f;
        #pragma unroll
        for (int j = 0; j < 16; j++) s += g_rs[j * 256 + m0 + tid];
        rst[tid] = s;
    }

    // loaders: E 1 cp16/thread, u 2 cp16/thread per chunk (K=128 chunks)
    const int rowE = tid >> 4, segE = tid & 15;
    const __half* aSrc = g_Ef + (m0 + rowE) * 512 + segE * 8;
    const uint32_t aDst = sb + (uint32_t)((rowE * P + segE * 8) * 2);
    const int uIdx0 = tid * 2, uIdx1 = tid * 2 + 1;
    const int kr0 = uIdx0 >> 3, sg0 = uIdx0 & 7;
    const int kr1 = uIdx1 >> 3, sg1 = uIdx1 & 7;
    const __half* bSrc0 = g_ub + kr0 * 1024 + n0b + sg0 * 8;
    const __half* bSrc1 = g_ub + kr1 * 1024 + n0b + sg1 * 8;
    const uint32_t bDst0 = sb + (uint32_t)(ET2B + (kr0 * P + sg0 * 8) * 2);
    const uint32_t bDst1 = sb + (uint32_t)(ET2B + (kr1 * P + sg1 * 8) * 2);

    #define G2_ISSUE(c) do { \
        const uint32_t _so = (c) * STG2B; \
        cp16(aDst + _so, aSrc + (c) * 128); \
        cp16(bDst0 + _so, bSrc0 + (c) * 128 * 1024); \
        cp16(bDst1 + _so, bSrc1 + (c) * 128 * 1024); \
        CP_COMMIT(); \
    } while (0)

    const uint32_t a2Off = (uint32_t)(((wm * 16 + lrow) * P + lk) * 2);
    const int li = lane & 7, kbit = (lane >> 3) & 1, nq = lane >> 4;
    const uint32_t tOff = (uint32_t)((((kbit * 8 + li) * P) + nq * 8) * 2);

    float acc[4][4] = {};

    G2_ISSUE(0); G2_ISSUE(1); G2_ISSUE(2); G2_ISSUE(3);
    #undef G2_ISSUE

    #pragma unroll
    for (int c = 0; c < 4; c++) {
        if (c == 0) CP_WAITN(3);
        else if (c == 1) CP_WAITN(2);
        else if (c == 2) CP_WAITN(1);
        else CP_WAITN(0);
        __syncthreads();
        const uint32_t st = sb + c * STG2B;
        const uint32_t stU = st + ET2B;
        #pragma unroll
        for (int j = 0; j < 2; j++) {
            const int ks = wk * 2 + j;
            uint32_t a[4], bq0[4], bq1[4];
            ldsm4(a, st + a2Off + ks * 32);
            ldsm4t(bq0, stU + tOff + ks * 16 * P * 2 + (wn * 32 + 0) * 2);
            ldsm4t(bq1, stU + tOff + ks * 16 * P * 2 + (wn * 32 + 16) * 2);
            mma_f16(acc[0], a, bq0[0], bq0[1]);
            mma_f16(acc[1], a, bq0[2], bq0[3]);
            mma_f16(acc[2], a, bq1[0], bq1[1]);
            mma_f16(acc[3], a, bq1[2], bq1[3]);
        }
    }

    // k-split reduction: sred2[12][32][16]
    float (*sred2)[32][16] = (float(*)[32][16])sredf;
    __syncthreads();
    if (wk != 0) {
        #pragma unroll
        for (int g = 0; g < 4; g++)
            #pragma unroll
            for (int i = 0; i < 4; i++)
                sred2[(wk - 1) * 4 + (wid & 3)][lane][g * 4 + i] = acc[g][i];
    }
    __syncthreads();

    if (wk == 0) {
        #pragma unroll
        for (int q = 0; q < 3; q++)
            #pragma unroll
            for (int g = 0; g < 4; g++)
                #pragma unroll
                for (int i = 0; i < 4; i++)
                    acc[g][i] += sred2[q * 4 + wid][lane][g * 4 + i];

        const int qr = lane >> 2;
        const int qc = (lane & 3) * 2;
        const int mrow0 = m0 + wm * 16 + qr;
        const int mrow1 = mrow0 + 8;
        const float r0v = rst[wm * 16 + qr];
        const float r1v = rst[wm * 16 + qr + 8];
        #pragma unroll
        for (int g = 0; g < 4; g++) {
            const int n = n0b + wn * 32 + g * 8 + qc;
            *(float2*)(Y + mrow0 * 1024 + n) = make_float2(acc[g][0] + r0v, acc[g][1] + r0v);
            *(float2*)(Y + mrow1 * 1024 + n) = make_float2(acc[g][2] + r1v, acc[g][3] + r1v);
        }
    }
}

// ============================================================
extern "C" void kernel_launch(void* const* d_in, const int* in_sizes, int n_in,
                              void* d_out, int out_size)
{
    const float* x = (const float*)d_in[0];   // 256 x 1024
    const float* W = (const float*)d_in[1];   // 512 x 1024
    const float* u = (const float*)d_in[2];   // 512 x 1024
    float* y = (float*)d_out;                 // 256 x 1024

    cudaFuncSetAttribute(fused_kernel, cudaFuncAttributeMaxDynamicSharedMemorySize, DSMEM);
    fused_kernel<<<128, 512, DSMEM>>>(x, W, u, y);
}